// round 1
// baseline (speedup 1.0000x reference)
#include <cuda_runtime.h>
#include <cuda_bf16.h>

#define HH 28
#define WW 28
#define PAD 3
#define PW 34      // 28 + 2*3
#define KK 7
#define NTAP 49
#define BATCH 512
#define NBR 8
#define FEAT 392   // 8 branches * 49

__device__ float g_feat[BATCH * FEAT];

// One block per (image b, branch r). Computes both SMorph layers + 4x4 avg pool
// entirely in shared memory, writes the 49 pooled features for this branch.
__global__ __launch_bounds__(256) void smorph_branch_kernel(
    const float* __restrict__ x,
    const float* __restrict__ sm_w,      // [8,2,7,7]
    const float* __restrict__ sm_alpha)  // [8,2]
{
    const int b   = blockIdx.x;
    const int r   = blockIdx.y;
    const int tid = threadIdx.x;

    __shared__ float sv[PW * PW];   // exp(alpha * in), halo = 1
    __shared__ float su[PW * PW];   // in * exp(alpha * in), halo = 0
    __shared__ float sy[HH * WW];   // layer output
    __shared__ float sc1[NTAP];     // exp(alpha * w[s])
    __shared__ float sc2[NTAP];     // w[s] * exp(alpha * w[s])

    // halo init (interior overwritten below; zero-padding <=> v=1, u=0)
    for (int i = tid; i < PW * PW; i += 256) { sv[i] = 1.0f; su[i] = 0.0f; }

    const float a0 = sm_alpha[r * 2 + 0];
    const float a1 = sm_alpha[r * 2 + 1];
    const float* xim = x + b * (HH * WW);

    // ---- layer 1 prep ----
    for (int i = tid; i < HH * WW; i += 256) {
        float xi = xim[i];
        float vv = __expf(a0 * xi);
        int pr = i / WW, pc = i % WW;
        int idx = (pr + PAD) * PW + pc + PAD;
        sv[idx] = vv;
        su[idx] = xi * vv;
    }
    if (tid < NTAP) {
        float wv = sm_w[(r * 2 + 0) * NTAP + tid];
        float c1 = __expf(a0 * wv);
        sc1[tid] = c1;
        sc2[tid] = c1 * wv;
    }
    __syncthreads();

    // ---- layer 1: 3 fused 7x7 convs ----
    for (int i = tid; i < HH * WW; i += 256) {
        int pr = i / WW, pc = i % WW;
        float num = 0.f, den = 0.f;
        #pragma unroll
        for (int dy = 0; dy < KK; dy++) {
            int ro = (pr + dy) * PW + pc;
            #pragma unroll
            for (int dx = 0; dx < KK; dx++) {
                float vv = sv[ro + dx];
                float uu = su[ro + dx];
                float c1 = sc1[dy * KK + dx];
                float c2 = sc2[dy * KK + dx];
                den = fmaf(c1, vv, den);
                num = fmaf(c1, uu, fmaf(c2, vv, num));
            }
        }
        sy[i] = num / den;
    }
    __syncthreads();

    // ---- layer 2 prep (reads sy, overwrites interior of sv/su; halo stays 1/0) ----
    for (int i = tid; i < HH * WW; i += 256) {
        float yi = sy[i];
        float vv = __expf(a1 * yi);
        int pr = i / WW, pc = i % WW;
        int idx = (pr + PAD) * PW + pc + PAD;
        sv[idx] = vv;
        su[idx] = yi * vv;
    }
    if (tid < NTAP) {
        float wv = sm_w[(r * 2 + 1) * NTAP + tid];
        float c1 = __expf(a1 * wv);
        sc1[tid] = c1;
        sc2[tid] = c1 * wv;
    }
    __syncthreads();

    // ---- layer 2 ----
    for (int i = tid; i < HH * WW; i += 256) {
        int pr = i / WW, pc = i % WW;
        float num = 0.f, den = 0.f;
        #pragma unroll
        for (int dy = 0; dy < KK; dy++) {
            int ro = (pr + dy) * PW + pc;
            #pragma unroll
            for (int dx = 0; dx < KK; dx++) {
                float vv = sv[ro + dx];
                float uu = su[ro + dx];
                float c1 = sc1[dy * KK + dx];
                float c2 = sc2[dy * KK + dx];
                den = fmaf(c1, vv, den);
                num = fmaf(c1, uu, fmaf(c2, vv, num));
            }
        }
        sy[i] = num / den;
    }
    __syncthreads();

    // ---- two 2x2 avg pools == one 4x4 avg pool -> [7,7] features ----
    if (tid < NTAP) {
        int pr = tid / 7, pc = tid % 7;
        float s = 0.f;
        #pragma unroll
        for (int dy = 0; dy < 4; dy++)
            #pragma unroll
            for (int dx = 0; dx < 4; dx++)
                s += sy[(pr * 4 + dy) * WW + pc * 4 + dx];
        // feat layout: [B, branch, 49]  (matches transpose(ys,(1,0,2,3,4)).reshape)
        g_feat[b * FEAT + r * NTAP + tid] = s * (1.0f / 16.0f);
    }
}

// Fused 3-layer sigmoid MLP, 16 batch rows per block.
#define RB 16
__global__ __launch_bounds__(256) void mlp_kernel(
    const float* __restrict__ W1, const float* __restrict__ b1,
    const float* __restrict__ W2, const float* __restrict__ b2,
    const float* __restrict__ W3, const float* __restrict__ b3,
    float* __restrict__ out)
{
    __shared__ float sf [RB][FEAT + 1];  // padded strides -> conflict-free column reads
    __shared__ float sh1[RB][121];
    __shared__ float sh2[RB][85];

    const int b0  = blockIdx.x * RB;
    const int tid = threadIdx.x;

    for (int i = tid; i < RB * FEAT; i += 256) {
        int rr = i / FEAT, cc = i % FEAT;
        sf[rr][cc] = g_feat[(b0 + rr) * FEAT + cc];
    }
    __syncthreads();

    const int rr = tid & (RB - 1);  // batch row within tile
    const int jb = tid >> 4;        // 0..15 output lane group

    // 392 -> 120
    for (int j = jb; j < 120; j += 16) {
        float acc = b1[j];
        const float* w = W1 + j * FEAT;
        #pragma unroll 8
        for (int i = 0; i < FEAT; i++) acc = fmaf(sf[rr][i], w[i], acc);
        sh1[rr][j] = 1.0f / (1.0f + __expf(-acc));
    }
    __syncthreads();

    // 120 -> 84
    for (int j = jb; j < 84; j += 16) {
        float acc = b2[j];
        const float* w = W2 + j * 120;
        #pragma unroll 8
        for (int i = 0; i < 120; i++) acc = fmaf(sh1[rr][i], w[i], acc);
        sh2[rr][j] = 1.0f / (1.0f + __expf(-acc));
    }
    __syncthreads();

    // 84 -> 10
    if (jb < 10) {
        const int j = jb;
        float acc = b3[j];
        const float* w = W3 + j * 84;
        #pragma unroll
        for (int i = 0; i < 84; i++) acc = fmaf(sh2[rr][i], w[i], acc);
        out[(b0 + rr) * 10 + j] = 1.0f / (1.0f + __expf(-acc));
    }
}

extern "C" void kernel_launch(void* const* d_in, const int* in_sizes, int n_in,
                              void* d_out, int out_size)
{
    const float* x        = (const float*)d_in[0];  // [512,1,28,28]
    const float* sm_w     = (const float*)d_in[1];  // [8,2,7,7]
    const float* sm_alpha = (const float*)d_in[2];  // [8,2]
    const float* W1       = (const float*)d_in[3];  // [120,392]
    const float* b1       = (const float*)d_in[4];
    const float* W2       = (const float*)d_in[5];  // [84,120]
    const float* b2       = (const float*)d_in[6];
    const float* W3       = (const float*)d_in[7];  // [10,84]
    const float* b3       = (const float*)d_in[8];
    float* out = (float*)d_out;                     // [512,10]

    dim3 gridA(BATCH, NBR);
    smorph_branch_kernel<<<gridA, 256>>>(x, sm_w, sm_alpha);

    mlp_kernel<<<BATCH / RB, 256>>>(W1, b1, W2, b2, W3, b3, out);
}

// round 2
// speedup vs baseline: 2.8206x; 2.8206x over previous
#include <cuda_runtime.h>
#include <cuda_bf16.h>

#define HH 28
#define WW 28
#define PAD 3
#define PW 35           // padded width (odd to spread smem banks)
#define KK 7
#define NTAP 49
#define BATCH 512
#define NBR 8
#define FEAT 392        // 8 branches * 49

#define IMG_PER_BLK 4
#define STRIPS 56       // (28/7 cols) x (28/2 rows) strips per image
#define THREADS_A (IMG_PER_BLK * STRIPS)   // 224 = 7 full warps

__device__ float g_feat[BATCH * FEAT];

typedef unsigned long long u64;

// SMorph factorization:  out = (Σ c1·u + Σ c2·v) / (Σ c1·v)
// with v = exp(a·x), u = x·v, c1 = exp(a·w), c2 = w·c1.
// Zero SAME-padding  <=>  halo cells (v,u) = (1,0).
//
// One block = 4 images x 1 branch. Each thread computes a 7-wide x 2-tall
// output strip with (v,u) interleaved float2 loads and packed f32x2 FMA.
__global__ void __launch_bounds__(THREADS_A)
smorph_branch_kernel(const float* __restrict__ x,
                     const float* __restrict__ sm_w,      // [8,2,7,7]
                     const float* __restrict__ sm_alpha)  // [8,2]
{
    extern __shared__ float smem[];
    float* svu = smem;                                   // [4][PW*PW][2]
    float* syb = smem + IMG_PER_BLK * PW * PW * 2;       // [4][784]
    float* scp = syb + IMG_PER_BLK * HH * WW;            // [49] float2 (c1,c1)
    float* sc2 = scp + 2 * NTAP;                         // [49]

    const int tid = threadIdx.x;
    const int b0  = blockIdx.x * IMG_PER_BLK;
    const int r   = blockIdx.y;

    const int img = tid / STRIPS;
    const int s   = tid % STRIPS;
    const int pr0 = (s / 4) * 2;   // strip top row   (0..26)
    const int pc0 = (s % 4) * 7;   // strip left col  (0,7,14,21)

    float2* myvu = (float2*)svu + img * (PW * PW);
    float*  mysy = syb + img * (HH * WW);
    const float* xim = x + (b0 + img) * (HH * WW);

    // init everything to halo value (v,u)=(1,0); interior overwritten per layer
    {
        float2* p = (float2*)svu;
        for (int i = tid; i < IMG_PER_BLK * PW * PW; i += THREADS_A)
            p[i] = make_float2(1.0f, 0.0f);
    }
    __syncthreads();

    #pragma unroll
    for (int L = 0; L < 2; L++) {
        const float aL = sm_alpha[r * 2 + L];

        // per-tap coefficients (shared across the 4 images: same branch)
        if (tid < NTAP) {
            float wv = sm_w[(r * 2 + L) * NTAP + tid];
            float c1 = __expf(aL * wv);
            scp[2 * tid]     = c1;
            scp[2 * tid + 1] = c1;
            sc2[tid]         = c1 * wv;
        }

        // interior fill: v = exp(a*in), u = in*v
        for (int i = s; i < HH * WW; i += STRIPS) {
            float xi = (L == 0) ? xim[i] : mysy[i];
            float vv = __expf(aL * xi);
            int pr = i / WW, pc = i % WW;
            myvu[(pr + PAD) * PW + pc + PAD] = make_float2(vv, xi * vv);
        }
        __syncthreads();

        // conv: 7x2 strip, 9 input rows, 13-wide float2 window
        u64   acc2[2][7];     // packed (den, num_u)
        float accw[2][7];     // Σ c2·v
        #pragma unroll
        for (int i = 0; i < 2; i++)
            #pragma unroll
            for (int j = 0; j < 7; j++) { acc2[i][j] = 0ull; accw[i][j] = 0.0f; }

        for (int dy = 0; dy < 9; dy++) {
            float2 t[13];
            const float2* rowp = myvu + (pr0 + dy) * PW + pc0;
            #pragma unroll
            for (int k = 0; k < 13; k++) t[k] = rowp[k];

            #pragma unroll
            for (int sr = 0; sr < 2; sr++) {
                int kr = dy - sr;
                if (kr >= 0 && kr < KK) {
                    #pragma unroll
                    for (int dx = 0; dx < KK; dx++) {
                        float2 cc = ((const float2*)scp)[kr * KK + dx];  // (c1,c1)
                        float  c2 = sc2[kr * KK + dx];
                        u64 ccu; asm("mov.b64 %0, {%1, %2};" : "=l"(ccu) : "f"(cc.x), "f"(cc.y));
                        #pragma unroll
                        for (int scx = 0; scx < 7; scx++) {
                            float2 vu = t[dx + scx];
                            u64 vuu; asm("mov.b64 %0, {%1, %2};" : "=l"(vuu) : "f"(vu.x), "f"(vu.y));
                            asm("fma.rn.f32x2 %0, %1, %2, %0;"
                                : "+l"(acc2[sr][scx]) : "l"(ccu), "l"(vuu));
                            accw[sr][scx] = fmaf(c2, vu.x, accw[sr][scx]);
                        }
                    }
                }
            }
        }
        __syncthreads();   // conv readers of svu & (L==1) sy readers done

        #pragma unroll
        for (int sr = 0; sr < 2; sr++)
            #pragma unroll
            for (int scx = 0; scx < 7; scx++) {
                float den, numu;
                asm("mov.b64 {%0, %1}, %2;" : "=f"(den), "=f"(numu) : "l"(acc2[sr][scx]));
                float num = numu + accw[sr][scx];
                mysy[(pr0 + sr) * WW + pc0 + scx] = __fdividef(num, den);
            }
        __syncthreads();
    }

    // 4x4 average pool (== two 2x2 pools) -> [7,7] features per branch
    if (s < NTAP) {
        int qr = s / 7, qc = s % 7;
        float acc = 0.0f;
        #pragma unroll
        for (int dy = 0; dy < 4; dy++)
            #pragma unroll
            for (int dx = 0; dx < 4; dx++)
                acc += mysy[(qr * 4 + dy) * WW + qc * 4 + dx];
        g_feat[(b0 + img) * FEAT + r * NTAP + s] = acc * (1.0f / 16.0f);
    }
}

__device__ __forceinline__ float sigf(float z) {
    return 1.0f / (1.0f + __expf(-z));
}

// Fused 3-layer sigmoid MLP. 4 batch rows per block, warp-parallel dots:
// lanes split the reduction dim (coalesced weight loads), shfl reduce.
#define MRB 4
__global__ void __launch_bounds__(256) mlp_kernel(
    const float* __restrict__ W1, const float* __restrict__ b1,
    const float* __restrict__ W2, const float* __restrict__ b2,
    const float* __restrict__ W3, const float* __restrict__ b3,
    float* __restrict__ out)
{
    __shared__ float sf [MRB][FEAT];
    __shared__ float sh1[MRB][120];
    __shared__ float sh2[MRB][84];

    const int b0   = blockIdx.x * MRB;
    const int tid  = threadIdx.x;
    const int warp = tid >> 5;
    const int lane = tid & 31;

    for (int i = tid; i < MRB * FEAT; i += 256)
        sf[i / FEAT][i % FEAT] = g_feat[b0 * FEAT + i];
    __syncthreads();

    // 392 -> 120
    for (int j = warp; j < 120; j += 8) {
        const float* w = W1 + j * FEAT;
        float a0 = 0.f, a1 = 0.f, a2 = 0.f, a3 = 0.f;
        #pragma unroll 4
        for (int i = lane; i < FEAT; i += 32) {
            float wv = w[i];
            a0 = fmaf(wv, sf[0][i], a0);
            a1 = fmaf(wv, sf[1][i], a1);
            a2 = fmaf(wv, sf[2][i], a2);
            a3 = fmaf(wv, sf[3][i], a3);
        }
        #pragma unroll
        for (int off = 16; off > 0; off >>= 1) {
            a0 += __shfl_down_sync(0xffffffffu, a0, off);
            a1 += __shfl_down_sync(0xffffffffu, a1, off);
            a2 += __shfl_down_sync(0xffffffffu, a2, off);
            a3 += __shfl_down_sync(0xffffffffu, a3, off);
        }
        if (lane == 0) {
            float bb = b1[j];
            sh1[0][j] = sigf(a0 + bb);
            sh1[1][j] = sigf(a1 + bb);
            sh1[2][j] = sigf(a2 + bb);
            sh1[3][j] = sigf(a3 + bb);
        }
    }
    __syncthreads();

    // 120 -> 84
    for (int j = warp; j < 84; j += 8) {
        const float* w = W2 + j * 120;
        float a0 = 0.f, a1 = 0.f, a2 = 0.f, a3 = 0.f;
        #pragma unroll
        for (int i = lane; i < 120; i += 32) {
            float wv = w[i];
            a0 = fmaf(wv, sh1[0][i], a0);
            a1 = fmaf(wv, sh1[1][i], a1);
            a2 = fmaf(wv, sh1[2][i], a2);
            a3 = fmaf(wv, sh1[3][i], a3);
        }
        #pragma unroll
        for (int off = 16; off > 0; off >>= 1) {
            a0 += __shfl_down_sync(0xffffffffu, a0, off);
            a1 += __shfl_down_sync(0xffffffffu, a1, off);
            a2 += __shfl_down_sync(0xffffffffu, a2, off);
            a3 += __shfl_down_sync(0xffffffffu, a3, off);
        }
        if (lane == 0) {
            float bb = b2[j];
            sh2[0][j] = sigf(a0 + bb);
            sh2[1][j] = sigf(a1 + bb);
            sh2[2][j] = sigf(a2 + bb);
            sh2[3][j] = sigf(a3 + bb);
        }
    }
    __syncthreads();

    // 84 -> 10
    for (int j = warp; j < 10; j += 8) {
        const float* w = W3 + j * 84;
        float a0 = 0.f, a1 = 0.f, a2 = 0.f, a3 = 0.f;
        #pragma unroll
        for (int i = lane; i < 84; i += 32) {
            float wv = w[i];
            a0 = fmaf(wv, sh2[0][i], a0);
            a1 = fmaf(wv, sh2[1][i], a1);
            a2 = fmaf(wv, sh2[2][i], a2);
            a3 = fmaf(wv, sh2[3][i], a3);
        }
        #pragma unroll
        for (int off = 16; off > 0; off >>= 1) {
            a0 += __shfl_down_sync(0xffffffffu, a0, off);
            a1 += __shfl_down_sync(0xffffffffu, a1, off);
            a2 += __shfl_down_sync(0xffffffffu, a2, off);
            a3 += __shfl_down_sync(0xffffffffu, a3, off);
        }
        if (lane == 0) {
            float bb = b3[j];
            out[(b0 + 0) * 10 + j] = sigf(a0 + bb);
            out[(b0 + 1) * 10 + j] = sigf(a1 + bb);
            out[(b0 + 2) * 10 + j] = sigf(a2 + bb);
            out[(b0 + 3) * 10 + j] = sigf(a3 + bb);
        }
    }
}

extern "C" void kernel_launch(void* const* d_in, const int* in_sizes, int n_in,
                              void* d_out, int out_size)
{
    const float* x        = (const float*)d_in[0];
    const float* sm_w     = (const float*)d_in[1];
    const float* sm_alpha = (const float*)d_in[2];
    const float* W1       = (const float*)d_in[3];
    const float* b1       = (const float*)d_in[4];
    const float* W2       = (const float*)d_in[5];
    const float* b2       = (const float*)d_in[6];
    const float* W3       = (const float*)d_in[7];
    const float* b3       = (const float*)d_in[8];
    float* out = (float*)d_out;

    const int smem_bytes =
        (IMG_PER_BLK * PW * PW * 2 + IMG_PER_BLK * HH * WW + 3 * NTAP) * (int)sizeof(float);
    static int attr_done = 0;
    if (!attr_done) {
        cudaFuncSetAttribute(smorph_branch_kernel,
                             cudaFuncAttributeMaxDynamicSharedMemorySize, smem_bytes);
        attr_done = 1;
    }

    dim3 gridA(BATCH / IMG_PER_BLK, NBR);   // (128, 8)
    smorph_branch_kernel<<<gridA, THREADS_A, smem_bytes>>>(x, sm_w, sm_alpha);

    mlp_kernel<<<BATCH / MRB, 256>>>(W1, b1, W2, b2, W3, b3, out);
}

// round 3
// speedup vs baseline: 3.0914x; 1.0960x over previous
#include <cuda_runtime.h>
#include <cuda_bf16.h>

#define HH 28
#define WW 28
#define PAD 3
#define PW 35           // padded width (odd -> spread smem banks)
#define KK 7
#define NTAP 49
#define BATCH 512
#define NBR 8
#define FEAT 392        // 8 branches * 49

#define IMG_PER_BLK 4
#define STRIPS 56       // (28/7 cols) x (28/2 rows) strips per image
#define THREADS_A (IMG_PER_BLK * STRIPS)   // 224 = 7 full warps

typedef unsigned long long u64;
union F2U { float2 f; u64 u; };

__device__ float g_feat[BATCH * FEAT];
__device__ float g_w1t[FEAT * 120];   // [392][120]
__device__ float g_w2t[120 * 84];     // [120][84]
__device__ float g_w3t[84 * 10];      // [84][10]

#define FMA2(acc, a, b) asm("fma.rn.f32x2 %0, %1, %2, %0;" : "+l"(acc) : "l"(a), "l"(b))

// SMorph factorization:  out = (sum c1*u + sum c2*v) / (sum c1*v)
// v = exp(a*x), u = x*v, c1 = exp(a*w), c2 = w*c1.  Zero SAME-pad <=> (v,u)=(1,0).
// One block = 4 images x 1 branch; each thread owns a 7x2 output strip.
__global__ void __launch_bounds__(THREADS_A)
smorph_branch_kernel(const float* __restrict__ x,
                     const float* __restrict__ sm_w,      // [8,2,7,7]
                     const float* __restrict__ sm_alpha,  // [8,2]
                     const float* __restrict__ W1,        // for folded transpose
                     const float* __restrict__ W2,
                     const float* __restrict__ W3)
{
    extern __shared__ float smem[];
    float* svu = smem;                              // [4][PW*PW][2]
    float* scp = svu + IMG_PER_BLK * PW * PW * 2;   // [49] float2 (c1,c1)
    float* sc2 = scp + 2 * NTAP;                    // [49]

    const int tid = threadIdx.x;
    const int b0  = blockIdx.x * IMG_PER_BLK;
    const int r   = blockIdx.y;

    // ---- folded one-shot weight transpose (spread over all 1024 blocks) ----
    {
        int gid = blockIdx.y * gridDim.x + blockIdx.x;
        int t = gid * THREADS_A + tid;
        if (t < FEAT * 120) {
            int i = t / 120, j = t % 120;
            g_w1t[t] = W1[j * FEAT + i];
        } else if (t < FEAT * 120 + 120 * 84) {
            int q = t - FEAT * 120; int i = q / 84, j = q % 84;
            g_w2t[q] = W2[j * 120 + i];
        } else if (t < FEAT * 120 + 120 * 84 + 840) {
            int q = t - FEAT * 120 - 120 * 84; int i = q / 10, j = q % 10;
            g_w3t[q] = W3[j * 84 + i];
        }
    }

    const int img = tid / STRIPS;
    const int s   = tid % STRIPS;
    const int pr0 = (s / 4) * 2;   // strip top row   (0..26)
    const int pc0 = (s % 4) * 7;   // strip left col  (0,7,14,21)

    float2* myvu = (float2*)svu + img * (PW * PW);
    const float* xim = x + (b0 + img) * (HH * WW);

    const float a0 = sm_alpha[r * 2 + 0];
    const float a1 = sm_alpha[r * 2 + 1];

    // init to halo (v,u)=(1,0); interior overwritten below
    {
        float2* p = (float2*)svu;
        for (int i = tid; i < IMG_PER_BLK * PW * PW; i += THREADS_A)
            p[i] = make_float2(1.0f, 0.0f);
    }
    // layer-0 coefficients
    if (tid < NTAP) {
        float wv = sm_w[(r * 2 + 0) * NTAP + tid];
        float c1 = __expf(a0 * wv);
        scp[2 * tid] = c1; scp[2 * tid + 1] = c1;
        sc2[tid] = c1 * wv;
    }
    __syncthreads();

    // layer-0 interior fill
    for (int i = s; i < HH * WW; i += STRIPS) {
        float xi = xim[i];
        float vv = __expf(a0 * xi);
        int pr = i / WW, pc = i % WW;
        myvu[(pr + PAD) * PW + pc + PAD] = make_float2(vv, xi * vv);
    }
    __syncthreads();

    float y[2][7];

    #pragma unroll 1
    for (int L = 0; L < 2; L++) {
        // ---- conv: 7x2 strip, 8 input rows, coefficient rows cached in regs ----
        u64   acc2[2][7];    // packed (den = sum c1*v, num_u = sum c1*u)
        float accw[2][7];    // sum c2*v
        #pragma unroll
        for (int i = 0; i < 2; i++)
            #pragma unroll
            for (int j = 0; j < 7; j++) { acc2[i][j] = 0ull; accw[i][j] = 0.0f; }

        F2U cc_cur[7], cc_prev[7];
        float c2_cur[7], c2_prev[7];

        #pragma unroll
        for (int dy = 0; dy < 8; dy++) {
            F2U t[13];
            const float2* rowp = myvu + (pr0 + dy) * PW + pc0;
            #pragma unroll
            for (int k = 0; k < 13; k++) t[k].f = rowp[k];

            if (dy < 7) {
                #pragma unroll
                for (int dx = 0; dx < 7; dx++) {
                    cc_cur[dx].f = ((const float2*)scp)[dy * 7 + dx];
                    c2_cur[dx]   = sc2[dy * 7 + dx];
                }
                // sr = 0 uses tap row ky = dy
                #pragma unroll
                for (int dx = 0; dx < 7; dx++) {
                    u64 c = cc_cur[dx].u; float c2 = c2_cur[dx];
                    #pragma unroll
                    for (int scx = 0; scx < 7; scx++) {
                        FMA2(acc2[0][scx], c, t[dx + scx].u);
                        accw[0][scx] = fmaf(c2, t[dx + scx].f.x, accw[0][scx]);
                    }
                }
            }
            if (dy >= 1) {
                // sr = 1 uses tap row ky = dy-1 (cached from previous iteration)
                #pragma unroll
                for (int dx = 0; dx < 7; dx++) {
                    u64 c = cc_prev[dx].u; float c2 = c2_prev[dx];
                    #pragma unroll
                    for (int scx = 0; scx < 7; scx++) {
                        FMA2(acc2[1][scx], c, t[dx + scx].u);
                        accw[1][scx] = fmaf(c2, t[dx + scx].f.x, accw[1][scx]);
                    }
                }
            }
            if (dy < 7) {
                #pragma unroll
                for (int dx = 0; dx < 7; dx++) {
                    cc_prev[dx] = cc_cur[dx]; c2_prev[dx] = c2_cur[dx];
                }
            }
        }

        #pragma unroll
        for (int sr = 0; sr < 2; sr++)
            #pragma unroll
            for (int scx = 0; scx < 7; scx++) {
                F2U a; a.u = acc2[sr][scx];
                float den = a.f.x;
                float num = a.f.y + accw[sr][scx];
                y[sr][scx] = __fdividef(num, den);
            }
        __syncthreads();   // all conv reads of svu / coeff smem done

        if (L == 0) {
            // write layer-1 (v,u) directly; refresh coefficients for layer 1
            if (tid < NTAP) {
                float wv = sm_w[(r * 2 + 1) * NTAP + tid];
                float c1 = __expf(a1 * wv);
                scp[2 * tid] = c1; scp[2 * tid + 1] = c1;
                sc2[tid] = c1 * wv;
            }
            #pragma unroll
            for (int sr = 0; sr < 2; sr++)
                #pragma unroll
                for (int scx = 0; scx < 7; scx++) {
                    float yi = y[sr][scx];
                    float vv = __expf(a1 * yi);
                    myvu[(pr0 + sr + PAD) * PW + pc0 + scx + PAD] =
                        make_float2(vv, yi * vv);
                }
        } else {
            // final layer: store y as plain floats overlaid on this image's svu
            float* syf = (float*)myvu;
            #pragma unroll
            for (int sr = 0; sr < 2; sr++)
                #pragma unroll
                for (int scx = 0; scx < 7; scx++)
                    syf[(pr0 + sr) * WW + pc0 + scx] = y[sr][scx];
        }
        __syncthreads();
    }

    // ---- 4x4 avg pool (== two 2x2 pools) -> [7,7] features ----
    if (s < NTAP) {
        const float* syf = (const float*)myvu;
        int qr = s / 7, qc = s % 7;
        float acc = 0.0f;
        #pragma unroll
        for (int dy = 0; dy < 4; dy++)
            #pragma unroll
            for (int dx = 0; dx < 4; dx++)
                acc += syf[(qr * 4 + dy) * WW + qc * 4 + dx];
        g_feat[(b0 + img) * FEAT + r * NTAP + s] = acc * (1.0f / 16.0f);
    }
}

__device__ __forceinline__ float sigf(float z) {
    return 1.0f / (1.0f + __expf(-z));
}

// Fused 3-layer sigmoid MLP on transposed weights.
// Block = 4 batch rows x 128 j-lanes; coalesced weight loads, broadcast LDS,
// pure per-thread FMA chains (no reductions).
#define MROWS 4
__global__ void __launch_bounds__(512) mlp_kernel(
    const float* __restrict__ b1,
    const float* __restrict__ b2,
    const float* __restrict__ b3,
    float* __restrict__ out)
{
    __shared__ float sf [MROWS][FEAT];
    __shared__ float sh1[MROWS][120];
    __shared__ float sh2[MROWS][84];

    const int tid = threadIdx.x;
    const int b0  = blockIdx.x * MROWS;
    const int rr  = tid >> 7;      // 0..3
    const int j   = tid & 127;     // 0..127

    for (int i = tid; i < MROWS * FEAT; i += 512)
        sf[i / FEAT][i % FEAT] = g_feat[b0 * FEAT + i];
    __syncthreads();

    // 392 -> 120
    if (j < 120) {
        float acc = b1[j];
        const float* w = g_w1t + j;
        #pragma unroll 8
        for (int i = 0; i < FEAT; i++) {
            acc = fmaf(sf[rr][i], *w, acc);
            w += 120;
        }
        sh1[rr][j] = sigf(acc);
    }
    __syncthreads();

    // 120 -> 84
    if (j < 84) {
        float acc = b2[j];
        const float* w = g_w2t + j;
        #pragma unroll 8
        for (int i = 0; i < 120; i++) {
            acc = fmaf(sh1[rr][i], *w, acc);
            w += 84;
        }
        sh2[rr][j] = sigf(acc);
    }
    __syncthreads();

    // 84 -> 10
    if (j < 10) {
        float acc = b3[j];
        const float* w = g_w3t + j;
        #pragma unroll 4
        for (int i = 0; i < 84; i++) {
            acc = fmaf(sh2[rr][i], *w, acc);
            w += 10;
        }
        out[(b0 + rr) * 10 + j] = sigf(acc);
    }
}

extern "C" void kernel_launch(void* const* d_in, const int* in_sizes, int n_in,
                              void* d_out, int out_size)
{
    const float* x        = (const float*)d_in[0];
    const float* sm_w     = (const float*)d_in[1];
    const float* sm_alpha = (const float*)d_in[2];
    const float* W1       = (const float*)d_in[3];
    const float* b1       = (const float*)d_in[4];
    const float* W2       = (const float*)d_in[5];
    const float* b2       = (const float*)d_in[6];
    const float* W3       = (const float*)d_in[7];
    const float* b3       = (const float*)d_in[8];
    float* out = (float*)d_out;

    const int smem_bytes =
        (IMG_PER_BLK * PW * PW * 2 + 3 * NTAP) * (int)sizeof(float);  // ~39.8KB

    dim3 gridA(BATCH / IMG_PER_BLK, NBR);   // (128, 8)
    smorph_branch_kernel<<<gridA, THREADS_A, smem_bytes>>>(
        x, sm_w, sm_alpha, W1, W2, W3);

    mlp_kernel<<<BATCH / MROWS, 512>>>(b1, b2, b3, out);
}

// round 4
// speedup vs baseline: 3.0998x; 1.0027x over previous
#include <cuda_runtime.h>
#include <cuda_bf16.h>

#define HH 28
#define WW 28
#define PAD 3
#define PW 35           // padded width (odd -> spread smem banks)
#define KK 7
#define NTAP 49
#define BATCH 512
#define NBR 8
#define FEAT 392        // 8 branches * 49

#define IMG_PER_BLK 4
#define STRIPS 56       // (28/7 cols) x (28/2 rows) strips per image
#define THREADS_A (IMG_PER_BLK * STRIPS)   // 224 = 7 full warps

typedef unsigned long long u64;
union F2U { float2 f; u64 u; };

__device__ float g_feat[BATCH * FEAT];
// float4-packed transposed weights: 4 consecutive K-steps per element.
__device__ float4 g_w1p[98 * 120];   // [i4][j]  w = W1[j][4*i4 .. 4*i4+3]
__device__ float4 g_w2p[30 * 84];    // [i4][j]  w = W2[j][4*i4 .. +3]
__device__ float4 g_w3p[21 * 10];    // [i4][j]  w = W3[j][4*i4 .. +3]

#define N_W1P (98 * 120)
#define N_W2P (30 * 84)
#define N_W3P (21 * 10)

#define FMA2(acc, a, b) asm("fma.rn.f32x2 %0, %1, %2, %0;" : "+l"(acc) : "l"(a), "l"(b))

// SMorph factorization:  out = (sum c1*u + sum c2*v) / (sum c1*v)
// v = exp(a*x), u = x*v, c1 = exp(a*w), c2 = w*c1.  Zero SAME-pad <=> (v,u)=(1,0).
// One block = 4 images x 1 branch; each thread owns a 7x2 output strip.
__global__ void __launch_bounds__(THREADS_A)
smorph_branch_kernel(const float* __restrict__ x,
                     const float* __restrict__ sm_w,      // [8,2,7,7]
                     const float* __restrict__ sm_alpha,  // [8,2]
                     const float* __restrict__ W1,        // for folded repack
                     const float* __restrict__ W2,
                     const float* __restrict__ W3)
{
    extern __shared__ float smem[];
    float* svu = smem;                              // [4][PW*PW][2]
    float* scp = svu + IMG_PER_BLK * PW * PW * 2;   // [49] float2 (c1,c1)
    float* sc2 = scp + 2 * NTAP;                    // [49]

    const int tid = threadIdx.x;
    const int b0  = blockIdx.x * IMG_PER_BLK;
    const int r   = blockIdx.y;

    // ---- folded one-shot weight repack (float4 of 4 consecutive K-steps) ----
    {
        int gid = blockIdx.y * gridDim.x + blockIdx.x;
        int t = gid * THREADS_A + tid;
        if (t < N_W1P) {
            int i4 = t / 120, j = t % 120;
            g_w1p[t] = *(const float4*)(W1 + j * FEAT + 4 * i4);
        } else if (t < N_W1P + N_W2P) {
            int q = t - N_W1P; int i4 = q / 84, j = q % 84;
            g_w2p[q] = *(const float4*)(W2 + j * 120 + 4 * i4);
        } else if (t < N_W1P + N_W2P + N_W3P) {
            int q = t - N_W1P - N_W2P; int i4 = q / 10, j = q % 10;
            g_w3p[q] = *(const float4*)(W3 + j * 84 + 4 * i4);
        }
    }

    const int img = tid / STRIPS;
    const int s   = tid % STRIPS;
    const int pr0 = (s / 4) * 2;   // strip top row   (0..26)
    const int pc0 = (s % 4) * 7;   // strip left col  (0,7,14,21)

    float2* myvu = (float2*)svu + img * (PW * PW);
    const float* xim = x + (b0 + img) * (HH * WW);

    const float a0 = sm_alpha[r * 2 + 0];
    const float a1 = sm_alpha[r * 2 + 1];

    // init to halo (v,u)=(1,0); interior overwritten below
    {
        float2* p = (float2*)svu;
        for (int i = tid; i < IMG_PER_BLK * PW * PW; i += THREADS_A)
            p[i] = make_float2(1.0f, 0.0f);
    }
    // layer-0 coefficients
    if (tid < NTAP) {
        float wv = sm_w[(r * 2 + 0) * NTAP + tid];
        float c1 = __expf(a0 * wv);
        scp[2 * tid] = c1; scp[2 * tid + 1] = c1;
        sc2[tid] = c1 * wv;
    }
    __syncthreads();

    // layer-0 interior fill
    for (int i = s; i < HH * WW; i += STRIPS) {
        float xi = xim[i];
        float vv = __expf(a0 * xi);
        int pr = i / WW, pc = i % WW;
        myvu[(pr + PAD) * PW + pc + PAD] = make_float2(vv, xi * vv);
    }
    __syncthreads();

    float y[2][7];

    #pragma unroll 1
    for (int L = 0; L < 2; L++) {
        // ---- conv: 7x2 strip, 8 input rows, coefficient rows cached in regs ----
        u64   acc2[2][7];    // packed (den = sum c1*v, num_u = sum c1*u)
        float accw[2][7];    // sum c2*v
        #pragma unroll
        for (int i = 0; i < 2; i++)
            #pragma unroll
            for (int j = 0; j < 7; j++) { acc2[i][j] = 0ull; accw[i][j] = 0.0f; }

        F2U cc_cur[7], cc_prev[7];
        float c2_cur[7], c2_prev[7];

        #pragma unroll
        for (int dy = 0; dy < 8; dy++) {
            F2U t[13];
            const float2* rowp = myvu + (pr0 + dy) * PW + pc0;
            #pragma unroll
            for (int k = 0; k < 13; k++) t[k].f = rowp[k];

            if (dy < 7) {
                #pragma unroll
                for (int dx = 0; dx < 7; dx++) {
                    cc_cur[dx].f = ((const float2*)scp)[dy * 7 + dx];
                    c2_cur[dx]   = sc2[dy * 7 + dx];
                }
                // sr = 0 uses tap row ky = dy
                #pragma unroll
                for (int dx = 0; dx < 7; dx++) {
                    u64 c = cc_cur[dx].u; float c2 = c2_cur[dx];
                    #pragma unroll
                    for (int scx = 0; scx < 7; scx++) {
                        FMA2(acc2[0][scx], c, t[dx + scx].u);
                        accw[0][scx] = fmaf(c2, t[dx + scx].f.x, accw[0][scx]);
                    }
                }
            }
            if (dy >= 1) {
                // sr = 1 uses tap row ky = dy-1 (cached from previous iteration)
                #pragma unroll
                for (int dx = 0; dx < 7; dx++) {
                    u64 c = cc_prev[dx].u; float c2 = c2_prev[dx];
                    #pragma unroll
                    for (int scx = 0; scx < 7; scx++) {
                        FMA2(acc2[1][scx], c, t[dx + scx].u);
                        accw[1][scx] = fmaf(c2, t[dx + scx].f.x, accw[1][scx]);
                    }
                }
            }
            if (dy < 7) {
                #pragma unroll
                for (int dx = 0; dx < 7; dx++) {
                    cc_prev[dx] = cc_cur[dx]; c2_prev[dx] = c2_cur[dx];
                }
            }
        }

        #pragma unroll
        for (int sr = 0; sr < 2; sr++)
            #pragma unroll
            for (int scx = 0; scx < 7; scx++) {
                F2U a; a.u = acc2[sr][scx];
                float den = a.f.x;
                float num = a.f.y + accw[sr][scx];
                y[sr][scx] = __fdividef(num, den);
            }
        __syncthreads();   // all conv reads of svu / coeff smem done

        if (L == 0) {
            // write layer-1 (v,u) directly; refresh coefficients for layer 1
            if (tid < NTAP) {
                float wv = sm_w[(r * 2 + 1) * NTAP + tid];
                float c1 = __expf(a1 * wv);
                scp[2 * tid] = c1; scp[2 * tid + 1] = c1;
                sc2[tid] = c1 * wv;
            }
            #pragma unroll
            for (int sr = 0; sr < 2; sr++)
                #pragma unroll
                for (int scx = 0; scx < 7; scx++) {
                    float yi = y[sr][scx];
                    float vv = __expf(a1 * yi);
                    myvu[(pr0 + sr + PAD) * PW + pc0 + scx + PAD] =
                        make_float2(vv, yi * vv);
                }
        } else {
            // final layer: store y as plain floats overlaid on this image's svu
            float* syf = (float*)myvu;
            #pragma unroll
            for (int sr = 0; sr < 2; sr++)
                #pragma unroll
                for (int scx = 0; scx < 7; scx++)
                    syf[(pr0 + sr) * WW + pc0 + scx] = y[sr][scx];
        }
        __syncthreads();
    }

    // ---- 4x4 avg pool (== two 2x2 pools) -> [7,7] features ----
    if (s < NTAP) {
        const float* syf = (const float*)myvu;
        int qr = s / 7, qc = s % 7;
        float acc = 0.0f;
        #pragma unroll
        for (int dy = 0; dy < 4; dy++)
            #pragma unroll
            for (int dx = 0; dx < 4; dx++)
                acc += syf[(qr * 4 + dy) * WW + qc * 4 + dx];
        g_feat[(b0 + img) * FEAT + r * NTAP + s] = acc * (1.0f / 16.0f);
    }
}

__device__ __forceinline__ float sigf(float z) {
    return 1.0f / (1.0f + __expf(-z));
}

// Fused 3-layer sigmoid MLP. Block = 128 threads = j-lanes, 4 batch rows per
// block held in 4 independent accumulator chains per thread. Weights come in
// float4 (4 K-steps per LDG.128, coalesced across j); activations via
// broadcast LDS.128. Independent array-indexed iterations -> pipelined loads.
#define MROWS 4
__global__ void __launch_bounds__(128) mlp_kernel(
    const float* __restrict__ b1,
    const float* __restrict__ b2,
    const float* __restrict__ b3,
    float* __restrict__ out)
{
    __shared__ float sf [MROWS][FEAT];
    __shared__ float sh1[MROWS][120];
    __shared__ float sh2[MROWS][84];

    const int tid = threadIdx.x;
    const int b0  = blockIdx.x * MROWS;

    // load features: 392 float4
    {
        const float4* src = (const float4*)(g_feat + b0 * FEAT);
        float4* dst = (float4*)sf;
        for (int i = tid; i < MROWS * FEAT / 4; i += 128)
            dst[i] = src[i];
    }
    __syncthreads();

    // ---- 392 -> 120 ----
    if (tid < 120) {
        const int j = tid;
        float bb = b1[j];
        float acc0 = bb, acc1 = bb, acc2 = bb, acc3 = bb;
        #pragma unroll 7
        for (int i4 = 0; i4 < 98; i4++) {
            float4 w  = g_w1p[i4 * 120 + j];
            float4 s0 = *(const float4*)&sf[0][i4 * 4];
            float4 s1 = *(const float4*)&sf[1][i4 * 4];
            float4 s2 = *(const float4*)&sf[2][i4 * 4];
            float4 s3 = *(const float4*)&sf[3][i4 * 4];
            acc0 = fmaf(w.x, s0.x, fmaf(w.y, s0.y, fmaf(w.z, s0.z, fmaf(w.w, s0.w, acc0))));
            acc1 = fmaf(w.x, s1.x, fmaf(w.y, s1.y, fmaf(w.z, s1.z, fmaf(w.w, s1.w, acc1))));
            acc2 = fmaf(w.x, s2.x, fmaf(w.y, s2.y, fmaf(w.z, s2.z, fmaf(w.w, s2.w, acc2))));
            acc3 = fmaf(w.x, s3.x, fmaf(w.y, s3.y, fmaf(w.z, s3.z, fmaf(w.w, s3.w, acc3))));
        }
        sh1[0][j] = sigf(acc0);
        sh1[1][j] = sigf(acc1);
        sh1[2][j] = sigf(acc2);
        sh1[3][j] = sigf(acc3);
    }
    __syncthreads();

    // ---- 120 -> 84 ----
    if (tid < 84) {
        const int j = tid;
        float bb = b2[j];
        float acc0 = bb, acc1 = bb, acc2 = bb, acc3 = bb;
        #pragma unroll 6
        for (int i4 = 0; i4 < 30; i4++) {
            float4 w  = g_w2p[i4 * 84 + j];
            float4 s0 = *(const float4*)&sh1[0][i4 * 4];
            float4 s1 = *(const float4*)&sh1[1][i4 * 4];
            float4 s2 = *(const float4*)&sh1[2][i4 * 4];
            float4 s3 = *(const float4*)&sh1[3][i4 * 4];
            acc0 = fmaf(w.x, s0.x, fmaf(w.y, s0.y, fmaf(w.z, s0.z, fmaf(w.w, s0.w, acc0))));
            acc1 = fmaf(w.x, s1.x, fmaf(w.y, s1.y, fmaf(w.z, s1.z, fmaf(w.w, s1.w, acc1))));
            acc2 = fmaf(w.x, s2.x, fmaf(w.y, s2.y, fmaf(w.z, s2.z, fmaf(w.w, s2.w, acc2))));
            acc3 = fmaf(w.x, s3.x, fmaf(w.y, s3.y, fmaf(w.z, s3.z, fmaf(w.w, s3.w, acc3))));
        }
        sh2[0][j] = sigf(acc0);
        sh2[1][j] = sigf(acc1);
        sh2[2][j] = sigf(acc2);
        sh2[3][j] = sigf(acc3);
    }
    __syncthreads();

    // ---- 84 -> 10 ----  (40 threads: one (row, j) scalar dot each)
    if (tid < 40) {
        const int j  = tid % 10;
        const int rr = tid / 10;
        float acc = b3[j];
        #pragma unroll 7
        for (int i4 = 0; i4 < 21; i4++) {
            float4 w = g_w3p[i4 * 10 + j];
            float4 s = *(const float4*)&sh2[rr][i4 * 4];
            acc = fmaf(w.x, s.x, fmaf(w.y, s.y, fmaf(w.z, s.z, fmaf(w.w, s.w, acc))));
        }
        out[(b0 + rr) * 10 + j] = sigf(acc);
    }
}

extern "C" void kernel_launch(void* const* d_in, const int* in_sizes, int n_in,
                              void* d_out, int out_size)
{
    const float* x        = (const float*)d_in[0];
    const float* sm_w     = (const float*)d_in[1];
    const float* sm_alpha = (const float*)d_in[2];
    const float* W1       = (const float*)d_in[3];
    const float* b1       = (const float*)d_in[4];
    const float* W2       = (const float*)d_in[5];
    const float* b2       = (const float*)d_in[6];
    const float* W3       = (const float*)d_in[7];
    const float* b3       = (const float*)d_in[8];
    float* out = (float*)d_out;

    const int smem_bytes =
        (IMG_PER_BLK * PW * PW * 2 + 3 * NTAP) * (int)sizeof(float);  // ~39.8KB

    dim3 gridA(BATCH / IMG_PER_BLK, NBR);   // (128, 8)
    smorph_branch_kernel<<<gridA, THREADS_A, smem_bytes>>>(
        x, sm_w, sm_alpha, W1, W2, W3);

    mlp_kernel<<<BATCH / MROWS, 128>>>(b1, b2, b3, out);
}

// round 5
// speedup vs baseline: 3.7541x; 1.2111x over previous
#include <cuda_runtime.h>
#include <cuda_bf16.h>

#define HH 28
#define WW 28
#define PAD 3
#define PW 35           // padded width (odd -> spread smem banks)
#define KK 7
#define NTAP 49
#define BATCH 512
#define NBR 8
#define FEAT 392        // 8 branches * 49

#define IMG_PER_BLK 4
#define STRIPS 56       // (28/7 cols) x (28/2 rows) strips per image
#define THREADS_A (IMG_PER_BLK * STRIPS)   // 224 = 7 full warps

typedef unsigned long long u64;
union F2U { float2 f; u64 u; };

__device__ float g_feat[BATCH * FEAT];
__device__ float g_w1t[FEAT * 120];   // transposed: [i][j]
__device__ float g_w2t[120 * 84];     // transposed: [i][j]

#define FMA2(acc, a, b) asm("fma.rn.f32x2 %0, %1, %2, %0;" : "+l"(acc) : "l"(a), "l"(b))

// SMorph factorization:  out = (sum c1*u + sum c2*v) / (sum c1*v)
// v = exp(a*x), u = x*v, c1 = exp(a*w), c2 = w*c1.  Zero SAME-pad <=> (v,u)=(1,0).
// One block = 4 images x 1 branch; each thread owns a 7x2 output strip.
__global__ void __launch_bounds__(THREADS_A)
smorph_branch_kernel(const float* __restrict__ x,
                     const float* __restrict__ sm_w,      // [8,2,7,7]
                     const float* __restrict__ sm_alpha,  // [8,2]
                     const float* __restrict__ W1,        // for folded transpose
                     const float* __restrict__ W2)
{
    extern __shared__ float smem[];
    float* svu = smem;                              // [4][PW*PW][2]
    float* scp = svu + IMG_PER_BLK * PW * PW * 2;   // [49] float2 (c1,c1)
    float* sc2 = scp + 2 * NTAP;                    // [49]

    const int tid = threadIdx.x;
    const int b0  = blockIdx.x * IMG_PER_BLK;
    const int r   = blockIdx.y;

    // ---- folded one-shot weight transpose (spread over all 1024 blocks) ----
    {
        int gid = blockIdx.y * gridDim.x + blockIdx.x;
        int t = gid * THREADS_A + tid;
        if (t < FEAT * 120) {
            int i = t / 120, j = t % 120;
            g_w1t[t] = W1[j * FEAT + i];
        } else if (t < FEAT * 120 + 120 * 84) {
            int q = t - FEAT * 120; int i = q / 84, j = q % 84;
            g_w2t[q] = W2[j * 120 + i];
        }
    }

    const int img = tid / STRIPS;
    const int s   = tid % STRIPS;
    const int pr0 = (s / 4) * 2;   // strip top row   (0..26)
    const int pc0 = (s % 4) * 7;   // strip left col  (0,7,14,21)

    float2* myvu = (float2*)svu + img * (PW * PW);
    const float* xim = x + (b0 + img) * (HH * WW);

    const float a0 = sm_alpha[r * 2 + 0];
    const float a1 = sm_alpha[r * 2 + 1];

    // init to halo (v,u)=(1,0); interior overwritten below
    {
        float2* p = (float2*)svu;
        for (int i = tid; i < IMG_PER_BLK * PW * PW; i += THREADS_A)
            p[i] = make_float2(1.0f, 0.0f);
    }
    // layer-0 coefficients
    if (tid < NTAP) {
        float wv = sm_w[(r * 2 + 0) * NTAP + tid];
        float c1 = __expf(a0 * wv);
        scp[2 * tid] = c1; scp[2 * tid + 1] = c1;
        sc2[tid] = c1 * wv;
    }
    __syncthreads();

    // layer-0 interior fill
    for (int i = s; i < HH * WW; i += STRIPS) {
        float xi = xim[i];
        float vv = __expf(a0 * xi);
        int pr = i / WW, pc = i % WW;
        myvu[(pr + PAD) * PW + pc + PAD] = make_float2(vv, xi * vv);
    }
    __syncthreads();

    float y[2][7];

    #pragma unroll 1
    for (int L = 0; L < 2; L++) {
        // ---- conv: 7x2 strip, 8 input rows, coefficient rows cached in regs ----
        u64   acc2[2][7];    // packed (den = sum c1*v, num_u = sum c1*u)
        float accw[2][7];    // sum c2*v
        #pragma unroll
        for (int i = 0; i < 2; i++)
            #pragma unroll
            for (int j = 0; j < 7; j++) { acc2[i][j] = 0ull; accw[i][j] = 0.0f; }

        F2U cc_cur[7], cc_prev[7];
        float c2_cur[7], c2_prev[7];

        #pragma unroll
        for (int dy = 0; dy < 8; dy++) {
            F2U t[13];
            const float2* rowp = myvu + (pr0 + dy) * PW + pc0;
            #pragma unroll
            for (int k = 0; k < 13; k++) t[k].f = rowp[k];

            if (dy < 7) {
                #pragma unroll
                for (int dx = 0; dx < 7; dx++) {
                    cc_cur[dx].f = ((const float2*)scp)[dy * 7 + dx];
                    c2_cur[dx]   = sc2[dy * 7 + dx];
                }
                // sr = 0 uses tap row ky = dy
                #pragma unroll
                for (int dx = 0; dx < 7; dx++) {
                    u64 c = cc_cur[dx].u; float c2 = c2_cur[dx];
                    #pragma unroll
                    for (int scx = 0; scx < 7; scx++) {
                        FMA2(acc2[0][scx], c, t[dx + scx].u);
                        accw[0][scx] = fmaf(c2, t[dx + scx].f.x, accw[0][scx]);
                    }
                }
            }
            if (dy >= 1) {
                // sr = 1 uses tap row ky = dy-1 (cached from previous iteration)
                #pragma unroll
                for (int dx = 0; dx < 7; dx++) {
                    u64 c = cc_prev[dx].u; float c2 = c2_prev[dx];
                    #pragma unroll
                    for (int scx = 0; scx < 7; scx++) {
                        FMA2(acc2[1][scx], c, t[dx + scx].u);
                        accw[1][scx] = fmaf(c2, t[dx + scx].f.x, accw[1][scx]);
                    }
                }
            }
            if (dy < 7) {
                #pragma unroll
                for (int dx = 0; dx < 7; dx++) {
                    cc_prev[dx] = cc_cur[dx]; c2_prev[dx] = c2_cur[dx];
                }
            }
        }

        #pragma unroll
        for (int sr = 0; sr < 2; sr++)
            #pragma unroll
            for (int scx = 0; scx < 7; scx++) {
                F2U a; a.u = acc2[sr][scx];
                float den = a.f.x;
                float num = a.f.y + accw[sr][scx];
                y[sr][scx] = __fdividef(num, den);
            }
        __syncthreads();   // all conv reads of svu / coeff smem done

        if (L == 0) {
            // write layer-1 (v,u) directly; refresh coefficients for layer 1
            if (tid < NTAP) {
                float wv = sm_w[(r * 2 + 1) * NTAP + tid];
                float c1 = __expf(a1 * wv);
                scp[2 * tid] = c1; scp[2 * tid + 1] = c1;
                sc2[tid] = c1 * wv;
            }
            #pragma unroll
            for (int sr = 0; sr < 2; sr++)
                #pragma unroll
                for (int scx = 0; scx < 7; scx++) {
                    float yi = y[sr][scx];
                    float vv = __expf(a1 * yi);
                    myvu[(pr0 + sr + PAD) * PW + pc0 + scx + PAD] =
                        make_float2(vv, yi * vv);
                }
        } else {
            // final layer: store y as plain floats overlaid on this image's svu
            float* syf = (float*)myvu;
            #pragma unroll
            for (int sr = 0; sr < 2; sr++)
                #pragma unroll
                for (int scx = 0; scx < 7; scx++)
                    syf[(pr0 + sr) * WW + pc0 + scx] = y[sr][scx];
        }
        __syncthreads();
    }

    // ---- 4x4 avg pool (== two 2x2 pools) -> [7,7] features ----
    if (s < NTAP) {
        const float* syf = (const float*)myvu;
        int qr = s / 7, qc = s % 7;
        float acc = 0.0f;
        #pragma unroll
        for (int dy = 0; dy < 4; dy++)
            #pragma unroll
            for (int dx = 0; dx < 4; dx++)
                acc += syf[(qr * 4 + dy) * WW + qc * 4 + dx];
        g_feat[(b0 + img) * FEAT + r * NTAP + s] = acc * (1.0f / 16.0f);
    }
}

__device__ __forceinline__ float sigf(float z) {
    return 1.0f / (1.0f + __expf(-z));
}

// Fused 3-layer sigmoid MLP, GEMM-style: weights cooperatively staged into
// shared memory in K-chunks (256 threads issue burst float4 LDGs -> high MLP,
// latency amortized), compute reads smem only. Thread = (j = tid>>1, row-pair
// = tid&1): warp covers 16 consecutive j x 2 row pairs -> conflict-free LDS.
#define MROWS 4
#define KCH 56
__global__ void __launch_bounds__(256) mlp_kernel(
    const float* __restrict__ b1,
    const float* __restrict__ b2,
    const float* __restrict__ b3,
    const float* __restrict__ W3,     // [10][84] original layout
    float* __restrict__ out)
{
    __shared__ float sf [MROWS][FEAT];   // features
    __shared__ float sh1[MROWS][120];
    __shared__ float sh2[MROWS][84];
    __shared__ float sw3[84 * 10];       // w3 transposed [i][j]
    __shared__ float swb[KCH * 120];     // staged weight chunk [kk][j]

    const int tid = threadIdx.x;
    const int b0  = blockIdx.x * MROWS;
    const int j   = tid >> 1;            // 0..127
    const int rp  = tid & 1;             // row pair: rows {2rp, 2rp+1}
    const int r0  = rp * 2, r1 = rp * 2 + 1;

    // features (float4) + W3 transpose-stage
    {
        const float4* src = (const float4*)(g_feat + b0 * FEAT);
        float4* dst = (float4*)sf;
        #pragma unroll
        for (int i = tid; i < MROWS * FEAT / 4; i += 256) dst[i] = src[i];
        for (int t = tid; t < 840; t += 256) {
            int ii = t / 10, jj = t % 10;
            sw3[t] = W3[jj * 84 + ii];
        }
    }
    __syncthreads();

    // ---- layer 1: 392 -> 120, K-chunks of 56 ----
    float aA0 = 0.f, aB0 = 0.f, aA1 = 0.f, aB1 = 0.f;
    if (j < 120) aA0 = b1[j];
    #pragma unroll 1
    for (int c = 0; c < FEAT / KCH; c++) {
        const float4* src = (const float4*)(g_w1t + c * (KCH * 120));
        #pragma unroll
        for (int i = tid; i < KCH * 120 / 4; i += 256)
            ((float4*)swb)[i] = src[i];
        __syncthreads();
        if (j < 120) {
            const int k0 = c * KCH;
            #pragma unroll 7
            for (int kk = 0; kk < KCH; kk += 2) {
                float  w0 = swb[kk * 120 + j];
                float  w1 = swb[(kk + 1) * 120 + j];
                float2 s0 = *(const float2*)&sf[r0][k0 + kk];
                float2 s1 = *(const float2*)&sf[r1][k0 + kk];
                aA0 = fmaf(w0, s0.x, aA0);  aB0 = fmaf(w1, s0.y, aB0);
                aA1 = fmaf(w0, s1.x, aA1);  aB1 = fmaf(w1, s1.y, aB1);
            }
        }
        __syncthreads();
    }
    if (j < 120) {
        sh1[r0][j] = sigf(aA0 + aB0);
        sh1[r1][j] = sigf(aA1 + aB1);
    }
    __syncthreads();

    // ---- layer 2: 120 -> 84, K-chunks {56,56,8} ----
    aA0 = aB0 = aA1 = aB1 = 0.f;
    if (j < 84) aA0 = b2[j];
    #pragma unroll 1
    for (int c = 0; c < 3; c++) {
        const int k0 = c * KCH;
        const int kn = (120 - k0 < KCH) ? (120 - k0) : KCH;
        const float4* src = (const float4*)(g_w2t + k0 * 84);
        const int n4 = kn * 84 / 4;
        for (int i = tid; i < n4; i += 256)
            ((float4*)swb)[i] = src[i];
        __syncthreads();
        if (j < 84) {
            for (int kk = 0; kk < kn; kk += 2) {
                float  w0 = swb[kk * 84 + j];
                float  w1 = swb[(kk + 1) * 84 + j];
                float2 s0 = *(const float2*)&sh1[r0][k0 + kk];
                float2 s1 = *(const float2*)&sh1[r1][k0 + kk];
                aA0 = fmaf(w0, s0.x, aA0);  aB0 = fmaf(w1, s0.y, aB0);
                aA1 = fmaf(w0, s1.x, aA1);  aB1 = fmaf(w1, s1.y, aB1);
            }
        }
        __syncthreads();
    }
    if (j < 84) {
        sh2[r0][j] = sigf(aA0 + aB0);
        sh2[r1][j] = sigf(aA1 + aB1);
    }
    __syncthreads();

    // ---- layer 3: 84 -> 10 (40 scalar dots from smem) ----
    if (tid < 40) {
        const int jj = tid % 10;
        const int rr = tid / 10;
        float a0 = b3[jj], a1 = 0.f;
        #pragma unroll 6
        for (int i = 0; i < 84; i += 2) {
            a0 = fmaf(sh2[rr][i],     sw3[i * 10 + jj],       a0);
            a1 = fmaf(sh2[rr][i + 1], sw3[(i + 1) * 10 + jj], a1);
        }
        out[(b0 + rr) * 10 + jj] = sigf(a0 + a1);
    }
}

extern "C" void kernel_launch(void* const* d_in, const int* in_sizes, int n_in,
                              void* d_out, int out_size)
{
    const float* x        = (const float*)d_in[0];
    const float* sm_w     = (const float*)d_in[1];
    const float* sm_alpha = (const float*)d_in[2];
    const float* W1       = (const float*)d_in[3];
    const float* b1       = (const float*)d_in[4];
    const float* W2       = (const float*)d_in[5];
    const float* b2       = (const float*)d_in[6];
    const float* W3       = (const float*)d_in[7];
    const float* b3       = (const float*)d_in[8];
    float* out = (float*)d_out;

    const int smem_bytes =
        (IMG_PER_BLK * PW * PW * 2 + 3 * NTAP) * (int)sizeof(float);  // ~39.8KB

    dim3 gridA(BATCH / IMG_PER_BLK, NBR);   // (128, 8)
    smorph_branch_kernel<<<gridA, THREADS_A, smem_bytes>>>(
        x, sm_w, sm_alpha, W1, W2);

    mlp_kernel<<<BATCH / MROWS, 256>>>(b1, b2, b3, W3, out);
}